// round 13
// baseline (speedup 1.0000x reference)
#include <cuda_runtime.h>
#include <cstdint>

typedef unsigned long long ull;

#define BB 4
#define LL 4096
#define HH 8
#define DD 64
#define SK 45
#define NT 45
#define BH (BB*HH)      /* 32 */
#define SEG 16
#define KSEG (LL/SEG)   /* 256 keys per segment */
#define KT 32           /* keys per smem tile */
#define PAD 68          /* floats per padded smem row (272B: conflict-free) */
#define CH 32           /* cumsum chunk length */
#define NCH (LL/CH)     /* 128 chunks */

// ---------------- scratch (__device__ globals: no allocation allowed) -------
__device__ float g_M[BB*HH*LL];              // 512 KB
__device__ int   g_Mtop[BB*HH*NT];
__device__ float g_logits[(size_t)BB*HH*NT*LL]; // 23.6 MB (logits, then probs)
__device__ float g_oatt[BB*HH*NT*DD];        // attention rows (atomic accum)
__device__ float g_csum[BB*HH*NCH*DD];       // chunk sums / exclusive prefixes

// ---------------- packed f32x2 helpers --------------------------------------
__device__ __forceinline__ void fma2(ull& d, ull a, ull b) {
    asm("fma.rn.f32x2 %0, %1, %2, %0;" : "+l"(d) : "l"(a), "l"(b));
}
__device__ __forceinline__ void add2(ull& a, ull b) {
    asm("add.rn.f32x2 %0, %0, %1;" : "+l"(a) : "l"(b));
}
__device__ __forceinline__ ull pack2(float a, float b) {
    ull r; asm("mov.b64 %0, {%1, %2};" : "=l"(r) : "f"(a), "f"(b)); return r;
}
__device__ __forceinline__ float f2lo(ull x) { return __uint_as_float((unsigned)x); }
__device__ __forceinline__ float f2hi(ull x) { return __uint_as_float((unsigned)(x >> 32)); }

// ============================================================================
// Kernel 1 (v3): M[b,h,l] = max_j(q·k_sample_j) - sum_j(q·k_sample_j)/L
// FOUR lanes per query (16-float quarter rows): ~40 regs, 4x threads,
// 4 independent LDG.128 per key per lane -> deep MLP against L2-resident K.
// All shuffles executed unconditionally by the full warp (no divergence).
// ============================================================================
__global__ __launch_bounds__(256) void k_m(const float* __restrict__ q,
                                           const float* __restrict__ k,
                                           const int* __restrict__ idx) {
    int t = blockIdx.x * 256 + threadIdx.x;      // 0 .. 4*B*H*L-1
    int quad = t & 3;                            // quarter of D
    int qy = t >> 2;                             // query id
    int l  = qy & (LL - 1);
    int bh = qy >> 12;
    int b = bh >> 3, h = bh & 7;

    const ulonglong2* q2 = (const ulonglong2*)
        (q + ((size_t)(b * LL + l) * HH + h) * DD + quad * 16);
    ull qd[8];
#pragma unroll
    for (int i = 0; i < 4; i++) { ulonglong2 v = q2[i]; qd[2*i] = v.x; qd[2*i+1] = v.y; }

    const int* idxrow = idx + l * SK;
    const float* kbase = k + ((size_t)b * LL * HH + h) * DD + quad * 16;

    float mx = -INFINITY, sm = 0.f;
#pragma unroll 3
    for (int j = 0; j < SK; j++) {
        int ki = __ldg(&idxrow[j]);
        const ulonglong2* k2 = (const ulonglong2*)(kbase + (size_t)ki * HH * DD);
        ulonglong2 va = k2[0], vb = k2[1], vc = k2[2], vd = k2[3];
        ull a0 = 0, a1 = 0;
        fma2(a0, qd[0], va.x); fma2(a1, qd[1], va.y);
        fma2(a0, qd[2], vb.x); fma2(a1, qd[3], vb.y);
        fma2(a0, qd[4], vc.x); fma2(a1, qd[5], vc.y);
        fma2(a0, qd[6], vd.x); fma2(a1, qd[7], vd.y);
        add2(a0, a1);
        float sh = f2lo(a0) + f2hi(a0);
        sh += __shfl_xor_sync(0xffffffffu, sh, 1);
        sh += __shfl_xor_sync(0xffffffffu, sh, 2);
        mx = fmaxf(mx, sh);
        sm += sh;
    }
    if (quad == 0) g_M[qy] = mx - sm * (1.0f / LL);
}

// ============================================================================
// Kernel 2: stable top-45 per (b,h) via iterative argmax (ties -> min index,
// matching jax.lax.top_k). Winners sorted ascending.
// ============================================================================
__global__ __launch_bounds__(256) void k_topk() {
    int bh  = blockIdx.x;
    int tid = threadIdx.x;   // 256
    __shared__ float wv[8];
    __shared__ int   wi[8];
    __shared__ int   winner;
    __shared__ int   winners[NT];

    float rv[16];
#pragma unroll
    for (int s = 0; s < 16; s++) rv[s] = g_M[(size_t)bh * LL + tid + s * 256];

    for (int it = 0; it < NT; it++) {
        float bv = -INFINITY; int bi = 1 << 30;
#pragma unroll
        for (int s = 0; s < 16; s++) {
            int i = tid + s * 256;
            float v = rv[s];
            if (v > bv || (v == bv && i < bi)) { bv = v; bi = i; }
        }
        for (int o = 16; o; o >>= 1) {
            float ov = __shfl_down_sync(0xffffffffu, bv, o);
            int   oi = __shfl_down_sync(0xffffffffu, bi, o);
            if (ov > bv || (ov == bv && oi < bi)) { bv = ov; bi = oi; }
        }
        if ((tid & 31) == 0) { wv[tid >> 5] = bv; wi[tid >> 5] = bi; }
        __syncthreads();
        if (tid == 0) {
            float fv = wv[0]; int fi = wi[0];
            for (int w = 1; w < 8; w++)
                if (wv[w] > fv || (wv[w] == fv && wi[w] < fi)) { fv = wv[w]; fi = wi[w]; }
            winner = fi;
            winners[it] = fi;
        }
        __syncthreads();
        int wn = winner;
#pragma unroll
        for (int s = 0; s < 16; s++)
            if (tid + s * 256 == wn) rv[s] = -INFINITY;
        __syncthreads();
    }
    if (tid == 0) {
        int w[NT];
        for (int i = 0; i < NT; i++) w[i] = winners[i];
        for (int i = 1; i < NT; i++) {
            int x = w[i], j = i - 1;
            while (j >= 0 && w[j] > x) { w[j + 1] = w[j]; j--; }
            w[j + 1] = x;
        }
        for (int i = 0; i < NT; i++) g_Mtop[bh * NT + i] = w[i];
    }
}

// ============================================================================
// Kernel 3a: logits[bh][u][k] = 0.125 * q_u · K_k   for k <= pos_u
// grid = (BH x SEG). block 256 = 64 u-slots x 4 key-lanes.
// ============================================================================
__global__ __launch_bounds__(256) void k_logits(const float* __restrict__ q,
                                                const float* __restrict__ kk) {
    int bh  = blockIdx.x >> 4;
    int seg = blockIdx.x & 15;
    int b = bh >> 3, h = bh & 7;
    __shared__ __align__(16) float qs[NT * PAD];
    __shared__ __align__(16) float ks[KT * PAD];
    __shared__ int pos_s[NT];
    int tid = threadIdx.x;

    if (tid < NT) pos_s[tid] = g_Mtop[bh * NT + tid];
    __syncthreads();
    for (int i = tid; i < NT * 16; i += 256) {
        int u = i >> 4, c = i & 15;
        const float4* qr =
            (const float4*)(q + ((size_t)(b * LL + pos_s[u]) * HH + h) * DD);
        *(float4*)&qs[u * PAD + c * 4] = qr[c];
    }
    __syncthreads();

    int u = tid >> 2, j = tid & 3;
    bool act = (u < NT);
    ull qd[32];
    int pos = -1;
    if (act) {
        pos = pos_s[u];
        const ulonglong2* q2 = (const ulonglong2*)&qs[u * PAD];
#pragma unroll
        for (int i = 0; i < 16; i++) { ulonglong2 v = q2[i]; qd[2*i] = v.x; qd[2*i+1] = v.y; }
    }

    int k0 = seg * KSEG;
    for (int tile = 0; tile < KSEG / KT; tile++) {
        int kb = k0 + tile * KT;
        __syncthreads();
        for (int i = tid; i < KT * 16; i += 256) {
            int r = i >> 4, c = i & 15;
            const float4* kr =
                (const float4*)(kk + ((size_t)(b * LL + kb + r) * HH + h) * DD);
            *(float4*)&ks[r * PAD + c * 4] = kr[c];
        }
        __syncthreads();
        if (act && kb <= pos) {
#pragma unroll 1
            for (int s = 0; s < KT / 4; s++) {
                int kl = j + s * 4;
                int kg = kb + kl;
                if (kg > pos) continue;
                const ulonglong2* k2 = (const ulonglong2*)&ks[kl * PAD];
                ull a0 = 0, a1 = 0, a2 = 0, a3 = 0;
#pragma unroll
                for (int i = 0; i < 8; i++) {
                    ulonglong2 v0 = k2[2*i], v1 = k2[2*i+1];
                    fma2(a0, qd[4*i+0], v0.x);
                    fma2(a1, qd[4*i+1], v0.y);
                    fma2(a2, qd[4*i+2], v1.x);
                    fma2(a3, qd[4*i+3], v1.y);
                }
                add2(a0, a1); add2(a2, a3); add2(a0, a2);
                g_logits[((size_t)(bh * NT + u)) * LL + kg] =
                    (f2lo(a0) + f2hi(a0)) * 0.125f;
            }
        }
    }
}

// ============================================================================
// Kernel 3b: in-place softmax over k in [0, pos] for each of the 1440 rows
// ============================================================================
__global__ __launch_bounds__(128) void k_softmax() {
    int row = blockIdx.x;              // bh*NT + u
    int pos = g_Mtop[row];
    int n = pos + 1;
    float* lg = g_logits + (size_t)row * LL;
    int tid = threadIdx.x;             // 128 = 4 warps
    __shared__ float red[4];

    float mx = -INFINITY;
    for (int i = tid; i < n; i += 128) mx = fmaxf(mx, lg[i]);
    for (int o = 16; o; o >>= 1) mx = fmaxf(mx, __shfl_xor_sync(0xffffffffu, mx, o));
    if ((tid & 31) == 0) red[tid >> 5] = mx;
    __syncthreads();
    mx = fmaxf(fmaxf(red[0], red[1]), fmaxf(red[2], red[3]));

    float sm = 0.f;
    for (int i = tid; i < n; i += 128) sm += expf(lg[i] - mx);
    for (int o = 16; o; o >>= 1) sm += __shfl_xor_sync(0xffffffffu, sm, o);
    __syncthreads();
    if ((tid & 31) == 0) red[tid >> 5] = sm;
    __syncthreads();
    sm = red[0] + red[1] + red[2] + red[3];

    float inv = 1.0f / sm;
    for (int i = tid; i < n; i += 128) lg[i] = expf(lg[i] - mx) * inv;
}

// ============================================================================
// zero the attention-output accumulator
// ============================================================================
__global__ void k_zero() {
    int i = blockIdx.x * 256 + threadIdx.x;
    if (i < BH * NT * DD) g_oatt[i] = 0.f;
}

// ============================================================================
// Kernel 3c: out_attn[bh][u][:] += sum_k p[u][k] * V[k][:]   (split-K, atomics)
// ============================================================================
__global__ __launch_bounds__(256) void k_pv(const float* __restrict__ v) {
    int bh  = blockIdx.x >> 4;
    int seg = blockIdx.x & 15;
    int b = bh >> 3, h = bh & 7;
    __shared__ __align__(16) float vs[KT * PAD];
    __shared__ float ps[NT * KT];
    __shared__ int pos_s[NT];
    int tid = threadIdx.x;

    if (tid < NT) pos_s[tid] = g_Mtop[bh * NT + tid];
    __syncthreads();

    int u = tid >> 2, dq = tid & 3;
    bool act = (u < NT);
    int pos = act ? pos_s[u] : -1;
    ull acc[8];
#pragma unroll
    for (int i = 0; i < 8; i++) acc[i] = 0;

    int k0 = seg * KSEG;
    for (int tile = 0; tile < KSEG / KT; tile++) {
        int kb = k0 + tile * KT;
        __syncthreads();
        for (int i = tid; i < KT * 16; i += 256) {
            int r = i >> 4, c = i & 15;
            const float4* vr =
                (const float4*)(v + ((size_t)(b * LL + kb + r) * HH + h) * DD);
            *(float4*)&vs[r * PAD + c * 4] = vr[c];
        }
        for (int i = tid; i < NT * KT; i += 256) {
            int uu = i >> 5, kl = i & 31;
            int kg = kb + kl;
            ps[i] = (kg <= pos_s[uu])
                      ? g_logits[((size_t)(bh * NT + uu)) * LL + kg] : 0.f;
        }
        __syncthreads();
        if (act && kb <= pos) {
#pragma unroll 1
            for (int kl = 0; kl < KT; kl++) {
                float p = ps[u * KT + kl];
                ull pp = pack2(p, p);
                const ulonglong2* vrow = (const ulonglong2*)&vs[kl * PAD + dq * 16];
                ulonglong2 v0 = vrow[0], v1 = vrow[1], v2 = vrow[2], v3 = vrow[3];
                fma2(acc[0], pp, v0.x); fma2(acc[1], pp, v0.y);
                fma2(acc[2], pp, v1.x); fma2(acc[3], pp, v1.y);
                fma2(acc[4], pp, v2.x); fma2(acc[5], pp, v2.y);
                fma2(acc[6], pp, v3.x); fma2(acc[7], pp, v3.y);
            }
        }
    }
    if (act) {
        float* dst = g_oatt + ((size_t)(bh * NT + u)) * DD + dq * 16;
#pragma unroll
        for (int i = 0; i < 8; i++) {
            atomicAdd(dst + 2 * i,     f2lo(acc[i]));
            atomicAdd(dst + 2 * i + 1, f2hi(acc[i]));
        }
    }
}

// ============================================================================
// cumsum(V) over L, chunked 3-phase scan (CH=32),
// with [B,L,H,D] -> [B,H,L,D] transpose on output
// ============================================================================
__global__ __launch_bounds__(64) void k_csum_a(const float* __restrict__ v) {
    int blk = blockIdx.x;                 // bh*NCH + ch
    int bh = blk >> 7, ch = blk & (NCH - 1);
    int b = bh >> 3, h = bh & 7;
    int d = threadIdx.x;
    float s = 0.f;
    const float* base = v + ((size_t)(b * LL + ch * CH) * HH + h) * DD + d;
#pragma unroll 4
    for (int i = 0; i < CH; i++) s += base[(size_t)i * HH * DD];
    g_csum[(size_t)blk * DD + d] = s;
}

__global__ __launch_bounds__(64) void k_csum_b() {
    int bh = blockIdx.x;
    int d = threadIdx.x;
    float run = 0.f;
    for (int ch = 0; ch < NCH; ch++) {
        size_t off = ((size_t)(bh * NCH + ch)) * DD + d;
        float t = g_csum[off];
        g_csum[off] = run;     // exclusive prefix
        run += t;
    }
}

__global__ __launch_bounds__(64) void k_csum_c(const float* __restrict__ v,
                                               float* __restrict__ out) {
    int blk = blockIdx.x;
    int bh = blk >> 7, ch = blk & (NCH - 1);
    int b = bh >> 3, h = bh & 7;
    int d = threadIdx.x;
    float acc = g_csum[(size_t)blk * DD + d];
    const float* base = v + ((size_t)(b * LL + ch * CH) * HH + h) * DD + d;
    float* obase = out + ((size_t)bh * LL + ch * CH) * DD + d;
#pragma unroll 4
    for (int i = 0; i < CH; i++) {
        acc += base[(size_t)i * HH * DD];
        obase[(size_t)i * DD] = acc;
    }
}

// ============================================================================
// Final scatter: overwrite selected rows with the attention results
// ============================================================================
__global__ __launch_bounds__(64) void k_scatter(float* __restrict__ out) {
    int row = blockIdx.x;                 // bh*NT + u
    int bh = row / NT;
    int pos = g_Mtop[row];
    int d = threadIdx.x;
    out[((size_t)bh * LL + pos) * DD + d] = g_oatt[(size_t)row * DD + d];
}

// ============================================================================
extern "C" void kernel_launch(void* const* d_in, const int* in_sizes, int n_in,
                              void* d_out, int out_size) {
    const float* q   = (const float*)d_in[0];
    const float* k   = (const float*)d_in[1];
    const float* v   = (const float*)d_in[2];
    const int*   idx = (const int*)d_in[3];
    float* out = (float*)d_out;
    (void)in_sizes; (void)n_in; (void)out_size;

    k_m      <<<4 * BB * HH * LL / 256, 256>>>(q, k, idx);
    k_topk   <<<BH, 256>>>();
    k_zero   <<<(BH * NT * DD + 255) / 256, 256>>>();
    k_logits <<<BH * SEG, 256>>>(q, k);
    k_softmax<<<BH * NT, 128>>>();
    k_pv     <<<BH * SEG, 256>>>(v);
    k_csum_a <<<BH * NCH, 64>>>(v);
    k_csum_b <<<BH, 64>>>();
    k_csum_c <<<BH * NCH, 64>>>(v, out);
    k_scatter<<<BH * NT, 64>>>(out);
}

// round 14
// speedup vs baseline: 1.1451x; 1.1451x over previous
#include <cuda_runtime.h>
#include <cstdint>

typedef unsigned long long ull;

#define BB 4
#define LL 4096
#define HH 8
#define DD 64
#define SK 45
#define NT 45
#define BH (BB*HH)      /* 32 */
#define SEG 16
#define KSEG (LL/SEG)   /* 256 keys per segment */
#define KT 32           /* keys per smem tile */
#define PAD 68          /* floats per padded smem row (272B: conflict-free) */
#define CH 32           /* cumsum chunk length */
#define NCH (LL/CH)     /* 128 chunks */
#define IPAD 46         /* idx smem row stride (ints) */

// ---------------- scratch (__device__ globals: no allocation allowed) -------
__device__ float g_M[BB*HH*LL];              // 512 KB
__device__ int   g_Mtop[BB*HH*NT];
__device__ float g_logits[(size_t)BB*HH*NT*LL]; // 23.6 MB (logits, then probs)
__device__ float g_oatt[BB*HH*NT*DD];        // attention rows (atomic accum)
__device__ float g_csum[BB*HH*NCH*DD];       // chunk sums / exclusive prefixes

// ---------------- packed f32x2 helpers --------------------------------------
__device__ __forceinline__ void fma2(ull& d, ull a, ull b) {
    asm("fma.rn.f32x2 %0, %1, %2, %0;" : "+l"(d) : "l"(a), "l"(b));
}
__device__ __forceinline__ void add2(ull& a, ull b) {
    asm("add.rn.f32x2 %0, %0, %1;" : "+l"(a) : "l"(b));
}
__device__ __forceinline__ ull pack2(float a, float b) {
    ull r; asm("mov.b64 %0, {%1, %2};" : "=l"(r) : "f"(a), "f"(b)); return r;
}
__device__ __forceinline__ float f2lo(ull x) { return __uint_as_float((unsigned)x); }
__device__ __forceinline__ float f2hi(ull x) { return __uint_as_float((unsigned)(x >> 32)); }

// ============================================================================
// Kernel 1 (v4): M[b,h,l] = max_j(q·k_sample_j) - sum_j(q·k_sample_j)/L
// 4 lanes per query with INTERLEAVED 16B chunks: lane j owns chunks j,j+4,
// j+8,j+12, so each warp LDG.128 covers a contiguous 64B block per gather row
// (nL ~8 lines instead of ~16 -> half the L1tex wavefront cost).
// idx rows staged in smem once per block (kills redundant scattered LDGs).
// ============================================================================
__global__ __launch_bounds__(256) void k_m(const float* __restrict__ q,
                                           const float* __restrict__ k,
                                           const int* __restrict__ idx) {
    __shared__ int sidx[64 * IPAD];
    int tid = threadIdx.x;
    int qy0 = blockIdx.x * 64;                   // 64 queries per block
    int bh  = qy0 >> 12;                          // block never straddles bh
    int l0  = qy0 & (LL - 1);
    int b = bh >> 3, h = bh & 7;

    for (int i = tid; i < 64 * SK; i += 256) {
        int ql = i / SK, j = i - ql * SK;
        sidx[ql * IPAD + j] = idx[(size_t)(l0 + ql) * SK + j];
    }
    __syncthreads();

    int quad = tid & 3;
    int ql   = tid >> 2;                          // 0..63
    const float* qrow = q + ((size_t)(b * LL + l0 + ql) * HH + h) * DD;
    ull qd[8];
#pragma unroll
    for (int i = 0; i < 4; i++) {
        ulonglong2 v = *(const ulonglong2*)(qrow + (quad + 4 * i) * 4);
        qd[2*i] = v.x; qd[2*i+1] = v.y;
    }

    const float* kbase = k + ((size_t)b * LL * HH + h) * DD;
    const int* srow = &sidx[ql * IPAD];

    float mx = -INFINITY, sm = 0.f;
#pragma unroll 3
    for (int j = 0; j < SK; j++) {
        int ki = srow[j];
        const float* krow = kbase + (size_t)ki * (HH * DD);
        ull a0 = 0, a1 = 0;
#pragma unroll
        for (int i = 0; i < 4; i++) {
            ulonglong2 v = *(const ulonglong2*)(krow + (quad + 4 * i) * 4);
            fma2(a0, qd[2*i],   v.x);
            fma2(a1, qd[2*i+1], v.y);
        }
        add2(a0, a1);
        float sh = f2lo(a0) + f2hi(a0);
        sh += __shfl_xor_sync(0xffffffffu, sh, 1);
        sh += __shfl_xor_sync(0xffffffffu, sh, 2);
        mx = fmaxf(mx, sh);
        sm += sh;
    }
    if (quad == 0) g_M[qy0 + ql] = mx - sm * (1.0f / LL);
}

// ============================================================================
// Kernel 2: stable top-45 per (b,h) via iterative argmax (ties -> min index,
// matching jax.lax.top_k). Winners sorted ascending.
// ============================================================================
__global__ __launch_bounds__(256) void k_topk() {
    int bh  = blockIdx.x;
    int tid = threadIdx.x;   // 256
    __shared__ float wv[8];
    __shared__ int   wi[8];
    __shared__ int   winner;
    __shared__ int   winners[NT];

    float rv[16];
#pragma unroll
    for (int s = 0; s < 16; s++) rv[s] = g_M[(size_t)bh * LL + tid + s * 256];

    for (int it = 0; it < NT; it++) {
        float bv = -INFINITY; int bi = 1 << 30;
#pragma unroll
        for (int s = 0; s < 16; s++) {
            int i = tid + s * 256;
            float v = rv[s];
            if (v > bv || (v == bv && i < bi)) { bv = v; bi = i; }
        }
        for (int o = 16; o; o >>= 1) {
            float ov = __shfl_down_sync(0xffffffffu, bv, o);
            int   oi = __shfl_down_sync(0xffffffffu, bi, o);
            if (ov > bv || (ov == bv && oi < bi)) { bv = ov; bi = oi; }
        }
        if ((tid & 31) == 0) { wv[tid >> 5] = bv; wi[tid >> 5] = bi; }
        __syncthreads();
        if (tid == 0) {
            float fv = wv[0]; int fi = wi[0];
            for (int w = 1; w < 8; w++)
                if (wv[w] > fv || (wv[w] == fv && wi[w] < fi)) { fv = wv[w]; fi = wi[w]; }
            winner = fi;
            winners[it] = fi;
        }
        __syncthreads();
        int wn = winner;
#pragma unroll
        for (int s = 0; s < 16; s++)
            if (tid + s * 256 == wn) rv[s] = -INFINITY;
        __syncthreads();
    }
    if (tid == 0) {
        int w[NT];
        for (int i = 0; i < NT; i++) w[i] = winners[i];
        for (int i = 1; i < NT; i++) {
            int x = w[i], j = i - 1;
            while (j >= 0 && w[j] > x) { w[j + 1] = w[j]; j--; }
            w[j + 1] = x;
        }
        for (int i = 0; i < NT; i++) g_Mtop[bh * NT + i] = w[i];
    }
}

// ============================================================================
// Kernel 3a (v2): logits[bh][u][k] = 0.125 * q_u · K_k   for k <= pos_u
// grid = (BH x SEG). block 256 = 64 u-groups x 4 lanes; lane j holds q chunks
// j,j+4,j+8,j+12 (8 ull -> ~40 regs, ~3x occupancy vs v1). Groups sweep the
// staged K tile in lockstep (smem broadcast, conflict-free 64B phases);
// group-mask shuffles per key (divergence-legal).
// ============================================================================
__global__ __launch_bounds__(256) void k_logits(const float* __restrict__ q,
                                                const float* __restrict__ kk) {
    int bh  = blockIdx.x >> 4;
    int seg = blockIdx.x & 15;
    int b = bh >> 3, h = bh & 7;
    __shared__ __align__(16) float ks[KT * PAD];
    __shared__ int pos_s[NT];
    int tid = threadIdx.x;

    if (tid < NT) pos_s[tid] = g_Mtop[bh * NT + tid];
    __syncthreads();

    int u = tid >> 2, j = tid & 3;
    unsigned gmask = 0xFu << ((tid & 31) & ~3);
    bool act = (u < NT);
    int pos = -1;
    ull qd[8];
    if (act) {
        pos = pos_s[u];
        const float* qrow = q + ((size_t)(b * LL + pos) * HH + h) * DD;
#pragma unroll
        for (int i = 0; i < 4; i++) {
            ulonglong2 v = *(const ulonglong2*)(qrow + (j + 4 * i) * 4);
            qd[2*i] = v.x; qd[2*i+1] = v.y;
        }
    }

    int k0 = seg * KSEG;
    for (int tile = 0; tile < KSEG / KT; tile++) {
        int kb = k0 + tile * KT;
        __syncthreads();
        for (int i = tid; i < KT * 16; i += 256) {
            int r = i >> 4, c = i & 15;
            const float4* kr =
                (const float4*)(kk + ((size_t)(b * LL + kb + r) * HH + h) * DD);
            *(float4*)&ks[r * PAD + c * 4] = kr[c];
        }
        __syncthreads();
        if (act && kb <= pos) {
            int kmax = pos - kb;                 // last valid local key
            if (kmax > KT - 1) kmax = KT - 1;
#pragma unroll 4
            for (int kl = 0; kl <= kmax; kl++) {
                const float* krow = &ks[kl * PAD];
                ull a0 = 0, a1 = 0;
#pragma unroll
                for (int i = 0; i < 4; i++) {
                    ulonglong2 v = *(const ulonglong2*)(krow + (j + 4 * i) * 4);
                    fma2(a0, qd[2*i],   v.x);
                    fma2(a1, qd[2*i+1], v.y);
                }
                add2(a0, a1);
                float sh = f2lo(a0) + f2hi(a0);
                sh += __shfl_xor_sync(gmask, sh, 1);
                sh += __shfl_xor_sync(gmask, sh, 2);
                if (j == 0)
                    g_logits[((size_t)(bh * NT + u)) * LL + kb + kl] = sh * 0.125f;
            }
        }
    }
}

// ============================================================================
// Kernel 3b: in-place softmax over k in [0, pos] for each of the 1440 rows
// ============================================================================
__global__ __launch_bounds__(128) void k_softmax() {
    int row = blockIdx.x;              // bh*NT + u
    int pos = g_Mtop[row];
    int n = pos + 1;
    float* lg = g_logits + (size_t)row * LL;
    int tid = threadIdx.x;             // 128 = 4 warps
    __shared__ float red[4];

    float mx = -INFINITY;
    for (int i = tid; i < n; i += 128) mx = fmaxf(mx, lg[i]);
    for (int o = 16; o; o >>= 1) mx = fmaxf(mx, __shfl_xor_sync(0xffffffffu, mx, o));
    if ((tid & 31) == 0) red[tid >> 5] = mx;
    __syncthreads();
    mx = fmaxf(fmaxf(red[0], red[1]), fmaxf(red[2], red[3]));

    float sm = 0.f;
    for (int i = tid; i < n; i += 128) sm += expf(lg[i] - mx);
    for (int o = 16; o; o >>= 1) sm += __shfl_xor_sync(0xffffffffu, sm, o);
    __syncthreads();
    if ((tid & 31) == 0) red[tid >> 5] = sm;
    __syncthreads();
    sm = red[0] + red[1] + red[2] + red[3];

    float inv = 1.0f / sm;
    for (int i = tid; i < n; i += 128) lg[i] = expf(lg[i] - mx) * inv;
}

// ============================================================================
// zero the attention-output accumulator
// ============================================================================
__global__ void k_zero() {
    int i = blockIdx.x * 256 + threadIdx.x;
    if (i < BH * NT * DD) g_oatt[i] = 0.f;
}

// ============================================================================
// Kernel 3c: out_attn[bh][u][:] += sum_k p[u][k] * V[k][:]   (split-K, atomics)
// ============================================================================
__global__ __launch_bounds__(256) void k_pv(const float* __restrict__ v) {
    int bh  = blockIdx.x >> 4;
    int seg = blockIdx.x & 15;
    int b = bh >> 3, h = bh & 7;
    __shared__ __align__(16) float vs[KT * PAD];
    __shared__ float ps[NT * KT];
    __shared__ int pos_s[NT];
    int tid = threadIdx.x;

    if (tid < NT) pos_s[tid] = g_Mtop[bh * NT + tid];
    __syncthreads();

    int u = tid >> 2, dq = tid & 3;
    bool act = (u < NT);
    int pos = act ? pos_s[u] : -1;
    ull acc[8];
#pragma unroll
    for (int i = 0; i < 8; i++) acc[i] = 0;

    int k0 = seg * KSEG;
    for (int tile = 0; tile < KSEG / KT; tile++) {
        int kb = k0 + tile * KT;
        __syncthreads();
        for (int i = tid; i < KT * 16; i += 256) {
            int r = i >> 4, c = i & 15;
            const float4* vr =
                (const float4*)(v + ((size_t)(b * LL + kb + r) * HH + h) * DD);
            *(float4*)&vs[r * PAD + c * 4] = vr[c];
        }
        for (int i = tid; i < NT * KT; i += 256) {
            int uu = i >> 5, kl = i & 31;
            int kg = kb + kl;
            ps[i] = (kg <= pos_s[uu])
                      ? g_logits[((size_t)(bh * NT + uu)) * LL + kg] : 0.f;
        }
        __syncthreads();
        if (act && kb <= pos) {
#pragma unroll 1
            for (int kl = 0; kl < KT; kl++) {
                float p = ps[u * KT + kl];
                ull pp = pack2(p, p);
                const ulonglong2* vrow = (const ulonglong2*)&vs[kl * PAD + dq * 16];
                ulonglong2 v0 = vrow[0], v1 = vrow[1], v2 = vrow[2], v3 = vrow[3];
                fma2(acc[0], pp, v0.x); fma2(acc[1], pp, v0.y);
                fma2(acc[2], pp, v1.x); fma2(acc[3], pp, v1.y);
                fma2(acc[4], pp, v2.x); fma2(acc[5], pp, v2.y);
                fma2(acc[6], pp, v3.x); fma2(acc[7], pp, v3.y);
            }
        }
    }
    if (act) {
        float* dst = g_oatt + ((size_t)(bh * NT + u)) * DD + dq * 16;
#pragma unroll
        for (int i = 0; i < 8; i++) {
            atomicAdd(dst + 2 * i,     f2lo(acc[i]));
            atomicAdd(dst + 2 * i + 1, f2hi(acc[i]));
        }
    }
}

// ============================================================================
// cumsum(V) over L, chunked 3-phase scan (CH=32),
// with [B,L,H,D] -> [B,H,L,D] transpose on output
// ============================================================================
__global__ __launch_bounds__(64) void k_csum_a(const float* __restrict__ v) {
    int blk = blockIdx.x;                 // bh*NCH + ch
    int bh = blk >> 7, ch = blk & (NCH - 1);
    int b = bh >> 3, h = bh & 7;
    int d = threadIdx.x;
    float s = 0.f;
    const float* base = v + ((size_t)(b * LL + ch * CH) * HH + h) * DD + d;
#pragma unroll 4
    for (int i = 0; i < CH; i++) s += base[(size_t)i * HH * DD];
    g_csum[(size_t)blk * DD + d] = s;
}

__global__ __launch_bounds__(64) void k_csum_b() {
    int bh = blockIdx.x;
    int d = threadIdx.x;
    float run = 0.f;
    for (int ch = 0; ch < NCH; ch++) {
        size_t off = ((size_t)(bh * NCH + ch)) * DD + d;
        float t = g_csum[off];
        g_csum[off] = run;     // exclusive prefix
        run += t;
    }
}

__global__ __launch_bounds__(64) void k_csum_c(const float* __restrict__ v,
                                               float* __restrict__ out) {
    int blk = blockIdx.x;
    int bh = blk >> 7, ch = blk & (NCH - 1);
    int b = bh >> 3, h = bh & 7;
    int d = threadIdx.x;
    float acc = g_csum[(size_t)blk * DD + d];
    const float* base = v + ((size_t)(b * LL + ch * CH) * HH + h) * DD + d;
    float* obase = out + ((size_t)bh * LL + ch * CH) * DD + d;
#pragma unroll 4
    for (int i = 0; i < CH; i++) {
        acc += base[(size_t)i * HH * DD];
        obase[(size_t)i * DD] = acc;
    }
}

// ============================================================================
// Final scatter: overwrite selected rows with the attention results
// ============================================================================
__global__ __launch_bounds__(64) void k_scatter(float* __restrict__ out) {
    int row = blockIdx.x;                 // bh*NT + u
    int bh = row / NT;
    int pos = g_Mtop[row];
    int d = threadIdx.x;
    out[((size_t)bh * LL + pos) * DD + d] = g_oatt[(size_t)row * DD + d];
}

// ============================================================================
extern "C" void kernel_launch(void* const* d_in, const int* in_sizes, int n_in,
                              void* d_out, int out_size) {
    const float* q   = (const float*)d_in[0];
    const float* k   = (const float*)d_in[1];
    const float* v   = (const float*)d_in[2];
    const int*   idx = (const int*)d_in[3];
    float* out = (float*)d_out;
    (void)in_sizes; (void)n_in; (void)out_size;

    k_m      <<<BB * HH * LL / 64, 256>>>(q, k, idx);
    k_topk   <<<BH, 256>>>();
    k_zero   <<<(BH * NT * DD + 255) / 256, 256>>>();
    k_logits <<<BH * SEG, 256>>>(q, k);
    k_softmax<<<BH * NT, 128>>>();
    k_pv     <<<BH * SEG, 256>>>(v);
    k_csum_a <<<BH * NCH, 64>>>(v);
    k_csum_b <<<BH, 64>>>();
    k_csum_c <<<BH * NCH, 64>>>(v, out);
    k_scatter<<<BH * NT, 64>>>(out);
}